// round 4
// baseline (speedup 1.0000x reference)
#include <cuda_runtime.h>
#include <cuda_fp16.h>
#include <cstdint>

#define B_ 16
#define T_ 256
#define IN_ 512
#define H_ 1024
#define G_ 4096
#define NL_ 8
#define BT_ 4096
#define NCTA 128
#define SMEM_SCAN 103168

// ---------------- device scratch (allocation-free) ----------------
__device__ __half g_Xh[(size_t)BT_ * IN_];
__device__ __half g_Wih0[(size_t)G_ * IN_];
__device__ __half g_WihR[(size_t)(NL_ - 1) * G_ * H_];
__device__ __half g_Whh[(size_t)NL_ * G_ * H_];
__device__ float  g_XG[(size_t)T_ * G_ * B_];
__device__ __half g_Xb0[(size_t)BT_ * H_];
__device__ __half g_Xb1[(size_t)BT_ * H_];
__device__ __half g_hbuf[2 * B_ * H_];
__device__ int    g_ctr[NL_ * T_];
__device__ float  g_finh[B_ * H_];
__device__ float  g_fc1o[B_ * 512];
__device__ float  g_fc2o[B_ * 256];

// ---------------- helpers ----------------
__device__ __forceinline__ void mma16816(float* d, const uint32_t* a, uint32_t b0, uint32_t b1) {
    asm volatile("mma.sync.aligned.m16n8k16.row.col.f32.f16.f16.f32 "
                 "{%0,%1,%2,%3}, {%4,%5,%6,%7}, {%8,%9}, {%0,%1,%2,%3};"
                 : "+f"(d[0]), "+f"(d[1]), "+f"(d[2]), "+f"(d[3])
                 : "r"(a[0]), "r"(a[1]), "r"(a[2]), "r"(a[3]), "r"(b0), "r"(b1));
}
__device__ __forceinline__ int ldacq(const int* p) {
    int v; asm volatile("ld.acquire.gpu.global.b32 %0, [%1];" : "=r"(v) : "l"(p) : "memory");
    return v;
}
__device__ __forceinline__ void addRel(int* p) {
    asm volatile("red.release.gpu.global.add.s32 [%0], %1;" :: "l"(p), "r"(1) : "memory");
}
__device__ __forceinline__ uint4 ldcg16(const void* p) {
    uint4 v;
    asm volatile("ld.global.cg.v4.u32 {%0,%1,%2,%3}, [%4];"
                 : "=r"(v.x), "=r"(v.y), "=r"(v.z), "=r"(v.w) : "l"(p));
    return v;
}
__device__ __forceinline__ float sigf(float x) { return 1.f / (1.f + __expf(-x)); }

// ---------------- utility kernels ----------------
__global__ void __launch_bounds__(256) k_f2h(const float* __restrict__ s, int dsel, size_t n) {
    __half* d = dsel == 0 ? g_Xh : dsel == 1 ? g_Wih0 : dsel == 2 ? g_WihR : g_Whh;
    size_t i = blockIdx.x * (size_t)blockDim.x + threadIdx.x;
    size_t st = (size_t)gridDim.x * blockDim.x;
    for (size_t k = i * 4; k < n; k += st * 4) {
        float4 v = *(const float4*)(s + k);
        __half2* o = (__half2*)(d + k);
        o[0] = __floats2half2_rn(v.x, v.y);
        o[1] = __floats2half2_rn(v.z, v.w);
    }
}
__global__ void __launch_bounds__(256) k_zero() {
    int i = blockIdx.x * blockDim.x + threadIdx.x;
    if (i < NL_ * T_) g_ctr[i] = 0;
    if (i < 2 * B_ * H_ / 8) ((uint4*)g_hbuf)[i] = make_uint4(0, 0, 0, 0);
}
__global__ void __launch_bounds__(256) k_zeroH() {
    int i = blockIdx.x * blockDim.x + threadIdx.x;
    if (i < B_ * H_ / 8) ((uint4*)g_hbuf)[i] = make_uint4(0, 0, 0, 0);
}

// ---------------- input projection GEMM ----------------
// C[row=b*T+t][j] = A[row]·W[j] + bih[j] + bhh[j], scattered to XG[t][j][b]
__global__ void __launch_bounds__(256) k_proj(int l, const float* __restrict__ bih,
                                              const float* __restrict__ bhh) {
    __shared__ __half sA[64 * 40], sB[64 * 40];
    const uint32_t* sAw = (const uint32_t*)sA;
    const uint32_t* sBw = (const uint32_t*)sB;
    int K = l ? H_ : IN_;
    const __half* Ag = (l == 0) ? g_Xh : ((l & 1) ? g_Xb0 : g_Xb1);
    const __half* Wg = l ? (g_WihR + (size_t)(l - 1) * G_ * H_) : g_Wih0;
    int tid = threadIdx.x, lane = tid & 31, w = tid >> 5;
    int wm = w >> 2, wn = w & 3, q = lane >> 2, r4 = lane & 3;
    int bM = blockIdx.y, bN = blockIdx.x;
    int lrow = tid >> 2, lch = tid & 3;
    const __half* Asrc = Ag + (size_t)(bM * 64 + lrow) * K + lch * 8;
    const __half* Bsrc = Wg + (size_t)(bN * 64 + lrow) * K + lch * 8;
    float acc[2][2][4];
#pragma unroll
    for (int a = 0; a < 2; a++)
        for (int b = 0; b < 2; b++)
            for (int r = 0; r < 4; r++) acc[a][b][r] = 0.f;
    for (int kt = 0; kt < K; kt += 32) {
        *(uint4*)(sA + lrow * 40 + lch * 8) = *(const uint4*)(Asrc + kt);
        *(uint4*)(sB + lrow * 40 + lch * 8) = *(const uint4*)(Bsrc + kt);
        __syncthreads();
#pragma unroll
        for (int ks = 0; ks < 2; ks++) {
            int kb2 = ks * 8;
#pragma unroll
            for (int mt = 0; mt < 2; mt++) {
                int aw = (wm * 32 + mt * 16 + q) * 20 + kb2 + r4;
                uint32_t af[4] = { sAw[aw], sAw[aw + 160], sAw[aw + 4], sAw[aw + 164] };
#pragma unroll
                for (int nt = 0; nt < 2; nt++) {
                    int bw = (wn * 16 + nt * 8 + q) * 20 + kb2 + r4;
                    mma16816(acc[mt][nt], af, sBw[bw], sBw[bw + 4]);
                }
            }
        }
        __syncthreads();
    }
#pragma unroll
    for (int mt = 0; mt < 2; mt++)
#pragma unroll
        for (int nt = 0; nt < 2; nt++)
#pragma unroll
            for (int r = 0; r < 4; r++) {
                int row = bM * 64 + wm * 32 + mt * 16 + q + ((r >> 1) << 3);
                int j = bN * 64 + wn * 16 + nt * 8 + r4 * 2 + (r & 1);
                int b = row >> 8, t = row & 255;
                g_XG[((size_t)t * G_ + j) * B_ + b] = acc[mt][nt][r] + bih[j] + bhh[j];
            }
}

// ---------------- persistent recurrent scan (one layer) ----------------
// 128 CTAs, CTA cid owns hidden units [cid*8, cid*8+8) = 32 gate rows.
__global__ void __launch_bounds__(256, 1) k_scan(int l) {
    extern __shared__ unsigned char smem[];
    float* sRed = (float*)smem;                 // 512 f
    float* sC = sRed + 512;                     // 128 f
    __half* sW = (__half*)(sC + 128);           // 32 x 1048
    __half* sA = sW + 32 * 1048;                // 16 x 1048
    const uint32_t* sWw = (const uint32_t*)sW;
    const uint32_t* sAw = (const uint32_t*)sA;
    int tid = threadIdx.x, cid = blockIdx.x;
    int lane = tid & 31, w = tid >> 5;
    int q = lane >> 2, r4 = lane & 3;
    const __half* Wl = g_Whh + (size_t)l * G_ * H_;
    __half* Xnext = (l & 1) ? g_Xb1 : g_Xb0;
    // load this CTA's Whh slice into smem (rows: [i f g o] x 8 local units)
    for (int u = tid; u < 4096; u += 256) {
        int lr = u >> 7, c8 = (u & 127) * 8;
        int grow = (lr >> 3) * H_ + cid * 8 + (lr & 7);
        *(uint4*)(sW + lr * 1048 + c8) = *(const uint4*)(Wl + (size_t)grow * H_ + c8);
    }
    if (tid < 128) sC[tid] = 0.f;
    int k0 = w << 7;  // warp k-range base (128 wide)
    int* ctr = g_ctr + l * T_;
    // epilogue thread constants
    int eb = tid >> 3, ehl = tid & 7, ehu = cid * 8 + ehl;
    for (int t = 0; t < T_; t++) {
        int rp = t & 1;
        sRed[tid] = 0.f; sRed[tid + 256] = 0.f;
        // prefetch XG gate biases early (latency hidden under h-load + mma)
        float xgi = 0.f, xgf = 0.f, xgg = 0.f, xgo = 0.f;
        if (tid < 128) {
            size_t xb = ((size_t)t * G_ + ehu) * B_ + eb;
            xgi = g_XG[xb];
            xgf = g_XG[xb + (size_t)1024 * B_];
            xgg = g_XG[xb + (size_t)2048 * B_];
            xgo = g_XG[xb + (size_t)3072 * B_];
        }
        const __half* hsrc = g_hbuf + rp * B_ * H_;
        for (int u = tid; u < 2048; u += 256) {
            int b = u >> 7, col = (u & 127) * 8;
            uint4 v = ldcg16(hsrc + b * H_ + col);
            *(uint4*)(sA + b * 1048 + col) = v;
        }
        __syncthreads();
        float acc[4][4];
#pragma unroll
        for (int i = 0; i < 4; i++)
            for (int j = 0; j < 4; j++) acc[i][j] = 0.f;
#pragma unroll
        for (int kk = 0; kk < 8; kk++) {
            int kb2 = (k0 + kk * 16) >> 1;
            int aw = q * 524 + kb2 + r4;
            uint32_t af[4] = { sAw[aw], sAw[aw + 8 * 524], sAw[aw + 4], sAw[aw + 4 + 8 * 524] };
#pragma unroll
            for (int nt = 0; nt < 4; nt++) {
                int bw = (nt * 8 + q) * 524 + kb2 + r4;
                mma16816(acc[nt], af, sWw[bw], sWw[bw + 4]);
            }
        }
#pragma unroll
        for (int nt = 0; nt < 4; nt++)
#pragma unroll
            for (int r = 0; r < 4; r++) {
                int m = q + ((r >> 1) << 3);
                int col = nt * 8 + r4 * 2 + (r & 1);
                atomicAdd(&sRed[m * 32 + col], acc[nt][r]);
            }
        __syncthreads();
        if (tid < 128) {
            float gi = sRed[eb * 32 + ehl]      + xgi;
            float gf = sRed[eb * 32 + 8 + ehl]  + xgf;
            float gg = sRed[eb * 32 + 16 + ehl] + xgg;
            float go = sRed[eb * 32 + 24 + ehl] + xgo;
            float c = sC[tid];
            c = sigf(gf) * c + sigf(gi) * tanhf(gg);
            float h = sigf(go) * tanhf(c);
            sC[tid] = c;
            __half hh = __float2half(h);
            g_hbuf[(1 - rp) * B_ * H_ + eb * H_ + ehu] = hh;
            Xnext[((size_t)eb * T_ + t) * H_ + ehu] = hh;
            if (l == NL_ - 1 && t == T_ - 1) g_finh[eb * H_ + ehu] = h;
        }
        __threadfence();
        __syncthreads();
        if (tid == 0) {
            addRel(&ctr[t]);
            while (ldacq(&ctr[t]) < NCTA) __nanosleep(60);
        }
        __syncthreads();
    }
}

// ---------------- FC head ----------------
__global__ void __launch_bounds__(256) k_fc(int isel, int osel, const float* __restrict__ wg,
                                            const float* __restrict__ bias, float* dext,
                                            int INn, int OUTn, int dorelu) {
    const float* in = isel == 0 ? g_finh : (isel == 1 ? g_fc1o : g_fc2o);
    float* out = osel == 3 ? dext : (osel == 1 ? g_fc1o : g_fc2o);
    int o = blockIdx.x * blockDim.x + threadIdx.x;
    if (o >= B_ * OUTn) return;
    int b = o / OUTn, j = o % OUTn;
    const float* ip = in + (size_t)b * INn;
    const float* wp = wg + (size_t)j * INn;
    float s = bias[j];
    for (int k = 0; k < INn; k += 4) {
        float4 a = *(const float4*)(ip + k);
        float4 v = *(const float4*)(wp + k);
        s += a.x * v.x + a.y * v.y + a.z * v.z + a.w * v.w;
    }
    if (dorelu) s = fmaxf(s, 0.f);
    out[b * OUTn + j] = s;
}

// ---------------- launch ----------------
extern "C" void kernel_launch(void* const* d_in, const int* in_sizes, int n_in,
                              void* d_out, int out_size) {
    const float* x    = (const float*)d_in[0];
    const float* Wih0 = (const float*)d_in[1];
    const float* WihR = (const float*)d_in[2];
    const float* Whh  = (const float*)d_in[3];
    const float* bih  = (const float*)d_in[4];
    const float* bhh  = (const float*)d_in[5];
    const float* f1w  = (const float*)d_in[6];
    const float* f1b  = (const float*)d_in[7];
    const float* f2w  = (const float*)d_in[8];
    const float* f2b  = (const float*)d_in[9];
    const float* f3w  = (const float*)d_in[10];
    const float* f3b  = (const float*)d_in[11];

    static int attr_set = 0;
    if (!attr_set) {
        cudaFuncSetAttribute(k_scan, cudaFuncAttributeMaxDynamicSharedMemorySize, SMEM_SCAN);
        attr_set = 1;
    }

    k_f2h<<<2048, 256>>>(x,    0, (size_t)BT_ * IN_);
    k_f2h<<<2048, 256>>>(Wih0, 1, (size_t)G_ * IN_);
    k_f2h<<<2048, 256>>>(WihR, 2, (size_t)(NL_ - 1) * G_ * H_);
    k_f2h<<<2048, 256>>>(Whh,  3, (size_t)NL_ * G_ * H_);
    k_zero<<<16, 256>>>();

    dim3 pg(64, 64);
    for (int l = 0; l < NL_; l++) {
        k_proj<<<pg, 256>>>(l, bih + l * G_, bhh + l * G_);
        k_zeroH<<<8, 256>>>();
        k_scan<<<NCTA, 256, SMEM_SCAN>>>(l);
    }
    k_fc<<<32, 256>>>(0, 1, f1w, f1b, nullptr, 1024, 512, 1);
    k_fc<<<16, 256>>>(1, 2, f2w, f2b, nullptr, 512, 256, 1);
    k_fc<<<1, 32>>>(2, 3, f3w, f3b, (float*)d_out, 256, 1, 0);
}

// round 5
// speedup vs baseline: 1.6095x; 1.6095x over previous
#include <cuda_runtime.h>
#include <cuda_fp16.h>
#include <cstdint>

#define B_ 16
#define T_ 256
#define IN_ 512
#define H_ 1024
#define G_ 4096
#define NL_ 8
#define BT_ 4096
#define NCTA 128

// scan smem: sRed 1056f + sC 128f + sW 32x1048h + sA 16x1048h
#define SMEM_SCAN (1056*4 + 128*4 + 32*1048*2 + 16*1048*2)
// proj smem: double-buffered A,B tiles 128x(64+8) halves each
#define PSTRIDE 72
#define SMEM_PROJ (4 * 128 * PSTRIDE * 2)

// ---------------- device scratch (allocation-free) ----------------
__device__ __half g_Xh[(size_t)BT_ * IN_];
__device__ __half g_Wih0[(size_t)G_ * IN_];
__device__ __half g_WihR[(size_t)(NL_ - 1) * G_ * H_];
__device__ __half g_Whh[(size_t)NL_ * G_ * H_];
__device__ float  g_XG[(size_t)T_ * B_ * G_];   // [t][b][gate*1024+hu]
__device__ __half g_Xb0[(size_t)BT_ * H_];
__device__ __half g_Xb1[(size_t)BT_ * H_];
__device__ __half g_hbuf[2 * B_ * H_];
__device__ int    g_ctr[NL_ * T_];
__device__ float  g_finh[B_ * H_];
__device__ float  g_fc1o[B_ * 512];
__device__ float  g_fc2o[B_ * 256];

// ---------------- helpers ----------------
__device__ __forceinline__ void mma16816(float* d, const uint32_t* a, uint32_t b0, uint32_t b1) {
    asm volatile("mma.sync.aligned.m16n8k16.row.col.f32.f16.f16.f32 "
                 "{%0,%1,%2,%3}, {%4,%5,%6,%7}, {%8,%9}, {%0,%1,%2,%3};"
                 : "+f"(d[0]), "+f"(d[1]), "+f"(d[2]), "+f"(d[3])
                 : "r"(a[0]), "r"(a[1]), "r"(a[2]), "r"(a[3]), "r"(b0), "r"(b1));
}
__device__ __forceinline__ int ldacq(const int* p) {
    int v; asm volatile("ld.acquire.gpu.global.b32 %0, [%1];" : "=r"(v) : "l"(p) : "memory");
    return v;
}
__device__ __forceinline__ void addRel(int* p) {
    asm volatile("red.release.gpu.global.add.s32 [%0], %1;" :: "l"(p), "r"(1) : "memory");
}
__device__ __forceinline__ uint4 ldcg16(const void* p) {
    uint4 v;
    asm volatile("ld.global.cg.v4.u32 {%0,%1,%2,%3}, [%4];"
                 : "=r"(v.x), "=r"(v.y), "=r"(v.z), "=r"(v.w) : "l"(p));
    return v;
}
__device__ __forceinline__ void cpa16(void* smem_dst, const void* gsrc) {
    uint32_t s = (uint32_t)__cvta_generic_to_shared(smem_dst);
    asm volatile("cp.async.cg.shared.global [%0], [%1], 16;" :: "r"(s), "l"(gsrc));
}
__device__ __forceinline__ float sigf(float x) { return 1.f / (1.f + __expf(-x)); }

// ---------------- utility kernels ----------------
__global__ void __launch_bounds__(256) k_f2h(const float* __restrict__ s, int dsel, size_t n) {
    __half* d = dsel == 0 ? g_Xh : dsel == 1 ? g_Wih0 : dsel == 2 ? g_WihR : g_Whh;
    size_t i = blockIdx.x * (size_t)blockDim.x + threadIdx.x;
    size_t st = (size_t)gridDim.x * blockDim.x;
    for (size_t k = i * 4; k < n; k += st * 4) {
        float4 v = *(const float4*)(s + k);
        __half2* o = (__half2*)(d + k);
        o[0] = __floats2half2_rn(v.x, v.y);
        o[1] = __floats2half2_rn(v.z, v.w);
    }
}
__global__ void __launch_bounds__(256) k_zero() {
    int i = blockIdx.x * blockDim.x + threadIdx.x;
    if (i < NL_ * T_) g_ctr[i] = 0;
}

// ---------------- input projection GEMM ----------------
// 128x128 tile, BK=64, cp.async double-buffered.
// C[row=b*T+t][j] = A[row]·W[j] + bih[j] + bhh[j] -> XG[t][b][j]
__global__ void __launch_bounds__(256) k_proj(int l, const float* __restrict__ bih,
                                              const float* __restrict__ bhh) {
    extern __shared__ __half psm[];
    __half* sA = psm;                       // [2][128*72]
    __half* sB = psm + 2 * 128 * PSTRIDE;   // [2][128*72]
    int K = l ? H_ : IN_;
    const __half* Ag = (l == 0) ? g_Xh : ((l & 1) ? g_Xb0 : g_Xb1);
    const __half* Wg = l ? (g_WihR + (size_t)(l - 1) * G_ * H_) : g_Wih0;
    int tid = threadIdx.x, lane = tid & 31, w = tid >> 5;
    int wm = w >> 1, wn = w & 1, q = lane >> 2, r4 = lane & 3;
    int bM = blockIdx.y, bN = blockIdx.x;

    // loader mapping: 4 chunks each for A and B per stage
    int lrow[4], lch[4];
#pragma unroll
    for (int p = 0; p < 4; p++) { int id = p * 256 + tid; lrow[p] = id >> 3; lch[p] = (id & 7) * 8; }

    float acc[2][8][4];
#pragma unroll
    for (int a = 0; a < 2; a++)
        for (int b = 0; b < 8; b++)
            for (int r = 0; r < 4; r++) acc[a][b][r] = 0.f;

    // prologue: load stage 0
#pragma unroll
    for (int p = 0; p < 4; p++) {
        cpa16(sA + lrow[p] * PSTRIDE + lch[p], Ag + (size_t)(bM * 128 + lrow[p]) * K + lch[p]);
        cpa16(sB + lrow[p] * PSTRIDE + lch[p], Wg + (size_t)(bN * 128 + lrow[p]) * K + lch[p]);
    }
    asm volatile("cp.async.commit_group;");

    int buf = 0;
    for (int kt = 0; kt < K; kt += 64, buf ^= 1) {
        bool more = (kt + 64) < K;
        if (more) {
            __half* dA = sA + (buf ^ 1) * 128 * PSTRIDE;
            __half* dB = sB + (buf ^ 1) * 128 * PSTRIDE;
#pragma unroll
            for (int p = 0; p < 4; p++) {
                cpa16(dA + lrow[p] * PSTRIDE + lch[p], Ag + (size_t)(bM * 128 + lrow[p]) * K + kt + 64 + lch[p]);
                cpa16(dB + lrow[p] * PSTRIDE + lch[p], Wg + (size_t)(bN * 128 + lrow[p]) * K + kt + 64 + lch[p]);
            }
            asm volatile("cp.async.commit_group;");
            asm volatile("cp.async.wait_group 1;");
        } else {
            asm volatile("cp.async.wait_group 0;");
        }
        __syncthreads();
        const uint32_t* sAw = (const uint32_t*)(sA + buf * 128 * PSTRIDE);
        const uint32_t* sBw = (const uint32_t*)(sB + buf * 128 * PSTRIDE);
        const int RS = PSTRIDE / 2;  // 36 u32 row stride
#pragma unroll
        for (int ks = 0; ks < 4; ks++) {
            int kb2 = ks * 8;
            uint32_t bf[8][2];
#pragma unroll
            for (int nt = 0; nt < 8; nt++) {
                int bw = (wn * 64 + nt * 8 + q) * RS + kb2 + r4;
                bf[nt][0] = sBw[bw]; bf[nt][1] = sBw[bw + 4];
            }
#pragma unroll
            for (int mt = 0; mt < 2; mt++) {
                int aw = (wm * 32 + mt * 16 + q) * RS + kb2 + r4;
                uint32_t af[4] = { sAw[aw], sAw[aw + 8 * RS], sAw[aw + 4], sAw[aw + 4 + 8 * RS] };
#pragma unroll
                for (int nt = 0; nt < 8; nt++) mma16816(acc[mt][nt], af, bf[nt][0], bf[nt][1]);
            }
        }
        __syncthreads();
    }
    // biases for this thread's 16 j-values
    float bj[8][2];
#pragma unroll
    for (int nt = 0; nt < 8; nt++)
#pragma unroll
        for (int e = 0; e < 2; e++) {
            int j = bN * 128 + wn * 64 + nt * 8 + r4 * 2 + e;
            bj[nt][e] = bih[j] + bhh[j];
        }
#pragma unroll
    for (int mt = 0; mt < 2; mt++)
#pragma unroll
        for (int nt = 0; nt < 8; nt++)
#pragma unroll
            for (int r = 0; r < 4; r++) {
                int row = bM * 128 + wm * 32 + mt * 16 + q + ((r >> 1) << 3);
                int j = bN * 128 + wn * 64 + nt * 8 + r4 * 2 + (r & 1);
                int b = row >> 8, t = row & 255;
                g_XG[((size_t)t * B_ + b) * G_ + j] = acc[mt][nt][r] + bj[nt][r & 1];
            }
}

// ---------------- persistent recurrent scan (one layer) ----------------
// 128 CTAs; CTA cid owns hidden units [cid*8, cid*8+8) = 32 gate rows.
// Warps: kw = w&1 (K half), nw = w>>1 (8-col n group) -> no-atomic reduce.
__global__ void __launch_bounds__(256, 1) k_scan(int l) {
    extern __shared__ unsigned char smem[];
    float* sRed = (float*)smem;                 // [2][16][33]
    float* sC = sRed + 1056;                    // 128 f
    __half* sW = (__half*)(sC + 128);           // 32 x 1048
    __half* sA = sW + 32 * 1048;                // 16 x 1048
    const uint32_t* sWw = (const uint32_t*)sW;
    const uint32_t* sAw = (const uint32_t*)sA;
    int tid = threadIdx.x, cid = blockIdx.x;
    int lane = tid & 31, w = tid >> 5;
    int q = lane >> 2, r4 = lane & 3;
    int kw = w & 1, nw = w >> 1;
    const __half* Wl = g_Whh + (size_t)l * G_ * H_;
    __half* Xnext = (l & 1) ? g_Xb1 : g_Xb0;
    // load this CTA's Whh slice (rows: [i f g o] x 8 local units)
    for (int u = tid; u < 4096; u += 256) {
        int lr = u >> 7, c8 = (u & 127) * 8;
        int grow = (lr >> 3) * H_ + cid * 8 + (lr & 7);
        *(uint4*)(sW + lr * 1048 + c8) = *(const uint4*)(Wl + (size_t)grow * H_ + c8);
    }
    if (tid < 128) sC[tid] = 0.f;
    int* ctr = g_ctr + l * T_;
    int eb = tid >> 3, ehl = tid & 7, ehu = cid * 8 + ehl;
    int kbase = kw * 256;  // u32 k offset (kw*512 halves)

    for (int t = 0; t < T_; t++) {
        int rp = t & 1;
        // prefetch gate pre-activations (hidden under h-load + mma)
        float xgi = 0.f, xgf = 0.f, xgg = 0.f, xgo = 0.f;
        if (tid < 128) {
            size_t xb = ((size_t)t * B_ + eb) * G_ + ehu;
            xgi = g_XG[xb];
            xgf = g_XG[xb + 1024];
            xgg = g_XG[xb + 2048];
            xgo = g_XG[xb + 3072];
        }
        // broadcast h into sA
        if (t == 0) {
            for (int u = tid; u < 2048; u += 256) {
                int b = u >> 7, col = (u & 127) * 8;
                *(uint4*)(sA + b * 1048 + col) = make_uint4(0, 0, 0, 0);
            }
        } else {
            const __half* hsrc = g_hbuf + rp * B_ * H_;
            for (int u = tid; u < 2048; u += 256) {
                int b = u >> 7, col = (u & 127) * 8;
                uint4 v = ldcg16(hsrc + b * H_ + col);
                *(uint4*)(sA + b * 1048 + col) = v;
            }
        }
        __syncthreads();
        float acc[4] = {0.f, 0.f, 0.f, 0.f};
#pragma unroll
        for (int kk = 0; kk < 32; kk++) {
            int kb2 = kbase + kk * 8;
            int aw = q * 524 + kb2 + r4;
            uint32_t af[4] = { sAw[aw], sAw[aw + 8 * 524], sAw[aw + 4], sAw[aw + 4 + 8 * 524] };
            int bw = (nw * 8 + q) * 524 + kb2 + r4;
            mma16816(acc, af, sWw[bw], sWw[bw + 4]);
        }
        // partials to disjoint smem slots
#pragma unroll
        for (int r = 0; r < 4; r++) {
            int m = q + ((r >> 1) << 3);
            int col = nw * 8 + r4 * 2 + (r & 1);
            sRed[(kw * 16 + m) * 33 + col] = acc[r];
        }
        __syncthreads();
        if (tid < 128) {
            int base0 = eb * 33, base1 = (16 + eb) * 33;
            float gi = sRed[base0 + ehl]      + sRed[base1 + ehl]      + xgi;
            float gf = sRed[base0 + 8 + ehl]  + sRed[base1 + 8 + ehl]  + xgf;
            float gg = sRed[base0 + 16 + ehl] + sRed[base1 + 16 + ehl] + xgg;
            float go = sRed[base0 + 24 + ehl] + sRed[base1 + 24 + ehl] + xgo;
            float c = sC[tid];
            c = sigf(gf) * c + sigf(gi) * tanhf(gg);
            float h = sigf(go) * tanhf(c);
            sC[tid] = c;
            __half hh = __float2half(h);
            g_hbuf[(1 - rp) * B_ * H_ + eb * H_ + ehu] = hh;
            Xnext[((size_t)eb * T_ + t) * H_ + ehu] = hh;
            if (l == NL_ - 1 && t == T_ - 1) g_finh[eb * H_ + ehu] = h;
        }
        __syncthreads();               // orders all stores before thread0's release
        if (tid == 0) {
            addRel(&ctr[t]);
            while (ldacq(&ctr[t]) < NCTA) {}
        }
        __syncthreads();
    }
}

// ---------------- FC head ----------------
__global__ void __launch_bounds__(256) k_fc(int isel, int osel, const float* __restrict__ wg,
                                            const float* __restrict__ bias, float* dext,
                                            int INn, int OUTn, int dorelu) {
    const float* in = isel == 0 ? g_finh : (isel == 1 ? g_fc1o : g_fc2o);
    float* out = osel == 3 ? dext : (osel == 1 ? g_fc1o : g_fc2o);
    int o = blockIdx.x * blockDim.x + threadIdx.x;
    if (o >= B_ * OUTn) return;
    int b = o / OUTn, j = o % OUTn;
    const float* ip = in + (size_t)b * INn;
    const float* wp = wg + (size_t)j * INn;
    float s = bias[j];
    for (int k = 0; k < INn; k += 4) {
        float4 a = *(const float4*)(ip + k);
        float4 v = *(const float4*)(wp + k);
        s += a.x * v.x + a.y * v.y + a.z * v.z + a.w * v.w;
    }
    if (dorelu) s = fmaxf(s, 0.f);
    out[b * OUTn + j] = s;
}

// ---------------- launch ----------------
extern "C" void kernel_launch(void* const* d_in, const int* in_sizes, int n_in,
                              void* d_out, int out_size) {
    const float* x    = (const float*)d_in[0];
    const float* Wih0 = (const float*)d_in[1];
    const float* WihR = (const float*)d_in[2];
    const float* Whh  = (const float*)d_in[3];
    const float* bih  = (const float*)d_in[4];
    const float* bhh  = (const float*)d_in[5];
    const float* f1w  = (const float*)d_in[6];
    const float* f1b  = (const float*)d_in[7];
    const float* f2w  = (const float*)d_in[8];
    const float* f2b  = (const float*)d_in[9];
    const float* f3w  = (const float*)d_in[10];
    const float* f3b  = (const float*)d_in[11];

    static int attr_set = 0;
    if (!attr_set) {
        cudaFuncSetAttribute(k_scan, cudaFuncAttributeMaxDynamicSharedMemorySize, SMEM_SCAN);
        cudaFuncSetAttribute(k_proj, cudaFuncAttributeMaxDynamicSharedMemorySize, SMEM_PROJ);
        attr_set = 1;
    }

    k_f2h<<<2048, 256>>>(x,    0, (size_t)BT_ * IN_);
    k_f2h<<<2048, 256>>>(Wih0, 1, (size_t)G_ * IN_);
    k_f2h<<<2048, 256>>>(WihR, 2, (size_t)(NL_ - 1) * G_ * H_);
    k_f2h<<<2048, 256>>>(Whh,  3, (size_t)NL_ * G_ * H_);
    k_zero<<<8, 256>>>();

    dim3 pg(32, 32);
    for (int l = 0; l < NL_; l++) {
        k_proj<<<pg, 256, SMEM_PROJ>>>(l, bih + l * G_, bhh + l * G_);
        k_scan<<<NCTA, 256, SMEM_SCAN>>>(l);
    }
    k_fc<<<32, 256>>>(0, 1, f1w, f1b, nullptr, 1024, 512, 1);
    k_fc<<<16, 256>>>(1, 2, f2w, f2b, nullptr, 512, 256, 1);
    k_fc<<<1, 32>>>(2, 3, f3w, f3b, (float*)d_out, 256, 1, 0);
}

// round 6
// speedup vs baseline: 1.8871x; 1.1725x over previous
#include <cuda_runtime.h>
#include <cuda_fp16.h>
#include <cstdint>

#define B_ 16
#define T_ 256
#define IN_ 512
#define H_ 1024
#define G_ 4096
#define NL_ 8
#define BT_ 4096
#define NCTA 128

// scan smem: sRed [8][16][40]f + sC 128f + sA 16x1048h
#define SMEM_SCAN (8*16*40*4 + 128*4 + 16*1048*2)
// proj smem: double-buffered A,B tiles 128x(64+8) halves each
#define PSTRIDE 72
#define SMEM_PROJ (4 * 128 * PSTRIDE * 2)

// ---------------- device scratch (allocation-free) ----------------
__device__ __half g_Xh[(size_t)BT_ * IN_];
__device__ __half g_Wih0[(size_t)G_ * IN_];
__device__ __half g_WihR[(size_t)(NL_ - 1) * G_ * H_];
__device__ __half g_Whh[(size_t)NL_ * G_ * H_];
__device__ float  g_XG[(size_t)T_ * B_ * G_];   // [t][b][gate*1024+hu]
__device__ __half g_Xb0[(size_t)BT_ * H_];
__device__ __half g_Xb1[(size_t)BT_ * H_];
__device__ __half g_hbuf[2 * B_ * H_];
__device__ int    g_ctr[NL_ * T_];
__device__ float  g_finh[B_ * H_];
__device__ float  g_fc1o[B_ * 512];
__device__ float  g_fc2o[B_ * 256];

// ---------------- helpers ----------------
__device__ __forceinline__ void mma16816(float* d, const uint32_t* a, uint32_t b0, uint32_t b1) {
    asm volatile("mma.sync.aligned.m16n8k16.row.col.f32.f16.f16.f32 "
                 "{%0,%1,%2,%3}, {%4,%5,%6,%7}, {%8,%9}, {%0,%1,%2,%3};"
                 : "+f"(d[0]), "+f"(d[1]), "+f"(d[2]), "+f"(d[3])
                 : "r"(a[0]), "r"(a[1]), "r"(a[2]), "r"(a[3]), "r"(b0), "r"(b1));
}
__device__ __forceinline__ int ldacq(const int* p) {
    int v; asm volatile("ld.acquire.gpu.global.b32 %0, [%1];" : "=r"(v) : "l"(p) : "memory");
    return v;
}
__device__ __forceinline__ void addRel(int* p) {
    asm volatile("red.release.gpu.global.add.s32 [%0], %1;" :: "l"(p), "r"(1) : "memory");
}
__device__ __forceinline__ uint4 ldcg16(const void* p) {
    uint4 v;
    asm volatile("ld.global.cg.v4.u32 {%0,%1,%2,%3}, [%4];"
                 : "=r"(v.x), "=r"(v.y), "=r"(v.z), "=r"(v.w) : "l"(p));
    return v;
}
__device__ __forceinline__ void cpa16(void* smem_dst, const void* gsrc) {
    uint32_t s = (uint32_t)__cvta_generic_to_shared(smem_dst);
    asm volatile("cp.async.cg.shared.global [%0], [%1], 16;" :: "r"(s), "l"(gsrc));
}
__device__ __forceinline__ uint32_t smaddr(const void* p) {
    return (uint32_t)__cvta_generic_to_shared(const_cast<void*>(p));
}
__device__ __forceinline__ void ldsm4(uint32_t* r, uint32_t a) {
    asm volatile("ldmatrix.sync.aligned.m8n8.x4.shared.b16 {%0,%1,%2,%3}, [%4];"
                 : "=r"(r[0]), "=r"(r[1]), "=r"(r[2]), "=r"(r[3]) : "r"(a));
}
__device__ __forceinline__ float sigf(float x) { return 1.f / (1.f + __expf(-x)); }

// ---------------- utility kernels ----------------
__global__ void __launch_bounds__(256) k_f2h(const float* __restrict__ s, int dsel, size_t n) {
    __half* d = dsel == 0 ? g_Xh : dsel == 1 ? g_Wih0 : dsel == 2 ? g_WihR : g_Whh;
    size_t i = blockIdx.x * (size_t)blockDim.x + threadIdx.x;
    size_t st = (size_t)gridDim.x * blockDim.x;
    for (size_t k = i * 4; k < n; k += st * 4) {
        float4 v = *(const float4*)(s + k);
        __half2* o = (__half2*)(d + k);
        o[0] = __floats2half2_rn(v.x, v.y);
        o[1] = __floats2half2_rn(v.z, v.w);
    }
}
__global__ void __launch_bounds__(256) k_zero() {
    int i = blockIdx.x * blockDim.x + threadIdx.x;
    if (i < NL_ * T_) g_ctr[i] = 0;
}

// ---------------- input projection GEMM ----------------
// 128x128 tile, BK=64, cp.async double-buffered.
// C[row=b*T+t][j] = A[row]·W[j] + bih[j] + bhh[j] -> XG[t][b][j]
__global__ void __launch_bounds__(256) k_proj(int l, const float* __restrict__ bih,
                                              const float* __restrict__ bhh) {
    extern __shared__ __half psm[];
    __half* sA = psm;                       // [2][128*72]
    __half* sB = psm + 2 * 128 * PSTRIDE;   // [2][128*72]
    int K = l ? H_ : IN_;
    const __half* Ag = (l == 0) ? g_Xh : ((l & 1) ? g_Xb0 : g_Xb1);
    const __half* Wg = l ? (g_WihR + (size_t)(l - 1) * G_ * H_) : g_Wih0;
    int tid = threadIdx.x, lane = tid & 31, w = tid >> 5;
    int wm = w >> 1, wn = w & 1, q = lane >> 2, r4 = lane & 3;
    int bM = blockIdx.y, bN = blockIdx.x;

    int lrow[4], lch[4];
#pragma unroll
    for (int p = 0; p < 4; p++) { int id = p * 256 + tid; lrow[p] = id >> 3; lch[p] = (id & 7) * 8; }

    float acc[2][8][4];
#pragma unroll
    for (int a = 0; a < 2; a++)
        for (int b = 0; b < 8; b++)
            for (int r = 0; r < 4; r++) acc[a][b][r] = 0.f;

#pragma unroll
    for (int p = 0; p < 4; p++) {
        cpa16(sA + lrow[p] * PSTRIDE + lch[p], Ag + (size_t)(bM * 128 + lrow[p]) * K + lch[p]);
        cpa16(sB + lrow[p] * PSTRIDE + lch[p], Wg + (size_t)(bN * 128 + lrow[p]) * K + lch[p]);
    }
    asm volatile("cp.async.commit_group;");

    int buf = 0;
    for (int kt = 0; kt < K; kt += 64, buf ^= 1) {
        bool more = (kt + 64) < K;
        if (more) {
            __half* dA = sA + (buf ^ 1) * 128 * PSTRIDE;
            __half* dB = sB + (buf ^ 1) * 128 * PSTRIDE;
#pragma unroll
            for (int p = 0; p < 4; p++) {
                cpa16(dA + lrow[p] * PSTRIDE + lch[p], Ag + (size_t)(bM * 128 + lrow[p]) * K + kt + 64 + lch[p]);
                cpa16(dB + lrow[p] * PSTRIDE + lch[p], Wg + (size_t)(bN * 128 + lrow[p]) * K + kt + 64 + lch[p]);
            }
            asm volatile("cp.async.commit_group;");
            asm volatile("cp.async.wait_group 1;");
        } else {
            asm volatile("cp.async.wait_group 0;");
        }
        __syncthreads();
        const uint32_t* sAw = (const uint32_t*)(sA + buf * 128 * PSTRIDE);
        const uint32_t* sBw = (const uint32_t*)(sB + buf * 128 * PSTRIDE);
        const int RS = PSTRIDE / 2;
#pragma unroll
        for (int ks = 0; ks < 4; ks++) {
            int kb2 = ks * 8;
            uint32_t bf[8][2];
#pragma unroll
            for (int nt = 0; nt < 8; nt++) {
                int bw = (wn * 64 + nt * 8 + q) * RS + kb2 + r4;
                bf[nt][0] = sBw[bw]; bf[nt][1] = sBw[bw + 4];
            }
#pragma unroll
            for (int mt = 0; mt < 2; mt++) {
                int aw = (wm * 32 + mt * 16 + q) * RS + kb2 + r4;
                uint32_t af[4] = { sAw[aw], sAw[aw + 8 * RS], sAw[aw + 4], sAw[aw + 4 + 8 * RS] };
#pragma unroll
                for (int nt = 0; nt < 8; nt++) mma16816(acc[mt][nt], af, bf[nt][0], bf[nt][1]);
            }
        }
        __syncthreads();
    }
    float bj[8][2];
#pragma unroll
    for (int nt = 0; nt < 8; nt++)
#pragma unroll
        for (int e = 0; e < 2; e++) {
            int j = bN * 128 + wn * 64 + nt * 8 + r4 * 2 + e;
            bj[nt][e] = bih[j] + bhh[j];
        }
#pragma unroll
    for (int mt = 0; mt < 2; mt++)
#pragma unroll
        for (int nt = 0; nt < 8; nt++)
#pragma unroll
            for (int r = 0; r < 4; r++) {
                int row = bM * 128 + wm * 32 + mt * 16 + q + ((r >> 1) << 3);
                int j = bN * 128 + wn * 64 + nt * 8 + r4 * 2 + (r & 1);
                int b = row >> 8, t = row & 255;
                g_XG[((size_t)t * B_ + b) * G_ + j] = acc[mt][nt][r] + bj[nt][r & 1];
            }
}

// ---------------- persistent recurrent scan (one layer) ----------------
// 128 CTAs; CTA cid owns hidden units [cid*8, cid*8+8) = 32 gate rows.
// 8-way K-split: warp w covers ALL 32 rows, K halves [w*128, w*128+128).
// Weights live in registers; A (h) loaded via ldmatrix from smem.
__global__ void __launch_bounds__(256, 1) k_scan(int l) {
    extern __shared__ unsigned char smem[];
    float* sRed = (float*)smem;                 // [8][16][40]
    float* sC = sRed + 8 * 16 * 40;             // 128 f
    __half* sA = (__half*)(sC + 128);           // 16 x 1048
    int tid = threadIdx.x, cid = blockIdx.x;
    int lane = tid & 31, w = tid >> 5;
    int q = lane >> 2, r4 = lane & 3;
    const __half* Wl = g_Whh + (size_t)l * G_ * H_;
    __half* Xnext = (l & 1) ? g_Xb1 : g_Xb0;

    // stationary weights -> registers, mma B-fragment layout
    // breg[nt][kk][e]: row = nt*1024 + cid*8 + q, halves = w*128 + kk*16 + 2*r4 + e*8
    uint32_t breg[4][8][2];
    {
        int kb = w * 128 + 2 * r4;
#pragma unroll
        for (int nt = 0; nt < 4; nt++) {
            const __half* rowp = Wl + (size_t)(nt * 1024 + cid * 8 + q) * H_ + kb;
#pragma unroll
            for (int kk = 0; kk < 8; kk++) {
                breg[nt][kk][0] = *(const uint32_t*)(rowp + kk * 16);
                breg[nt][kk][1] = *(const uint32_t*)(rowp + kk * 16 + 8);
            }
        }
    }
    if (tid < 128) sC[tid] = 0.f;
    int* ctr = g_ctr + l * T_;
    int eb = tid >> 3, ehl = tid & 7, ehu = cid * 8 + ehl;
    // ldmatrix source: row = lane&15, col halves = w*128 + ((lane>>4)<<3)
    uint32_t lds_base = smaddr(sA + (lane & 15) * 1048 + w * 128 + ((lane >> 4) << 3));

    for (int t = 0; t < T_; t++) {
        int rp = t & 1;
        // prefetch gate pre-activations (latency hidden under h-load + mma)
        float xgi = 0.f, xgf = 0.f, xgg = 0.f, xgo = 0.f;
        if (tid < 128) {
            size_t xb = ((size_t)t * B_ + eb) * G_ + ehu;
            xgi = g_XG[xb];
            xgf = g_XG[xb + 1024];
            xgg = g_XG[xb + 2048];
            xgo = g_XG[xb + 3072];
        }
        // broadcast h into sA
        if (t == 0) {
            for (int u = tid; u < 2048; u += 256) {
                int b = u >> 7, col = (u & 127) * 8;
                *(uint4*)(sA + b * 1048 + col) = make_uint4(0, 0, 0, 0);
            }
        } else {
            const __half* hsrc = g_hbuf + rp * B_ * H_;
            for (int u = tid; u < 2048; u += 256) {
                int b = u >> 7, col = (u & 127) * 8;
                uint4 v = ldcg16(hsrc + b * H_ + col);
                *(uint4*)(sA + b * 1048 + col) = v;
            }
        }
        __syncthreads();
        float acc[4][4];
#pragma unroll
        for (int i = 0; i < 4; i++)
            for (int j = 0; j < 4; j++) acc[i][j] = 0.f;
#pragma unroll
        for (int kk = 0; kk < 8; kk++) {
            uint32_t a[4];
            ldsm4(a, lds_base + kk * 32);   // 16 halves = 32 bytes
#pragma unroll
            for (int nt = 0; nt < 4; nt++)
                mma16816(acc[nt], a, breg[nt][kk][0], breg[nt][kk][1]);
        }
        // partials to disjoint smem
#pragma unroll
        for (int nt = 0; nt < 4; nt++)
#pragma unroll
            for (int r = 0; r < 4; r++) {
                int m = q + ((r >> 1) << 3);
                int col = nt * 8 + r4 * 2 + (r & 1);
                sRed[(w * 16 + m) * 40 + col] = acc[nt][r];
            }
        __syncthreads();
        if (tid < 128) {
            float gi = xgi, gf = xgf, gg = xgg, go = xgo;
#pragma unroll
            for (int ww = 0; ww < 8; ww++) {
                int base = (ww * 16 + eb) * 40;
                gi += sRed[base + ehl];
                gf += sRed[base + 8 + ehl];
                gg += sRed[base + 16 + ehl];
                go += sRed[base + 24 + ehl];
            }
            float c = sC[tid];
            c = sigf(gf) * c + sigf(gi) * tanhf(gg);
            float h = sigf(go) * tanhf(c);
            sC[tid] = c;
            __half hh = __float2half(h);
            g_hbuf[(1 - rp) * B_ * H_ + eb * H_ + ehu] = hh;
            Xnext[((size_t)eb * T_ + t) * H_ + ehu] = hh;
            if (l == NL_ - 1 && t == T_ - 1) g_finh[eb * H_ + ehu] = h;
        }
        __syncthreads();               // orders all stores before thread0's release
        if (tid == 0) {
            addRel(&ctr[t]);
            while (ldacq(&ctr[t]) < NCTA) {}
        }
        __syncthreads();
    }
}

// ---------------- FC head ----------------
__global__ void __launch_bounds__(256) k_fc(int isel, int osel, const float* __restrict__ wg,
                                            const float* __restrict__ bias, float* dext,
                                            int INn, int OUTn, int dorelu) {
    const float* in = isel == 0 ? g_finh : (isel == 1 ? g_fc1o : g_fc2o);
    float* out = osel == 3 ? dext : (osel == 1 ? g_fc1o : g_fc2o);
    int o = blockIdx.x * blockDim.x + threadIdx.x;
    if (o >= B_ * OUTn) return;
    int b = o / OUTn, j = o % OUTn;
    const float* ip = in + (size_t)b * INn;
    const float* wp = wg + (size_t)j * INn;
    float s = bias[j];
    for (int k = 0; k < INn; k += 4) {
        float4 a = *(const float4*)(ip + k);
        float4 v = *(const float4*)(wp + k);
        s += a.x * v.x + a.y * v.y + a.z * v.z + a.w * v.w;
    }
    if (dorelu) s = fmaxf(s, 0.f);
    out[b * OUTn + j] = s;
}

// ---------------- launch ----------------
extern "C" void kernel_launch(void* const* d_in, const int* in_sizes, int n_in,
                              void* d_out, int out_size) {
    const float* x    = (const float*)d_in[0];
    const float* Wih0 = (const float*)d_in[1];
    const float* WihR = (const float*)d_in[2];
    const float* Whh  = (const float*)d_in[3];
    const float* bih  = (const float*)d_in[4];
    const float* bhh  = (const float*)d_in[5];
    const float* f1w  = (const float*)d_in[6];
    const float* f1b  = (const float*)d_in[7];
    const float* f2w  = (const float*)d_in[8];
    const float* f2b  = (const float*)d_in[9];
    const float* f3w  = (const float*)d_in[10];
    const float* f3b  = (const float*)d_in[11];

    static int attr_set = 0;
    if (!attr_set) {
        cudaFuncSetAttribute(k_scan, cudaFuncAttributeMaxDynamicSharedMemorySize, SMEM_SCAN);
        cudaFuncSetAttribute(k_proj, cudaFuncAttributeMaxDynamicSharedMemorySize, SMEM_PROJ);
        attr_set = 1;
    }

    k_f2h<<<2048, 256>>>(x,    0, (size_t)BT_ * IN_);
    k_f2h<<<2048, 256>>>(Wih0, 1, (size_t)G_ * IN_);
    k_f2h<<<2048, 256>>>(WihR, 2, (size_t)(NL_ - 1) * G_ * H_);
    k_f2h<<<2048, 256>>>(Whh,  3, (size_t)NL_ * G_ * H_);
    k_zero<<<8, 256>>>();

    dim3 pg(32, 32);
    for (int l = 0; l < NL_; l++) {
        k_proj<<<pg, 256, SMEM_PROJ>>>(l, bih + l * G_, bhh + l * G_);
        k_scan<<<NCTA, 256, SMEM_SCAN>>>(l);
    }
    k_fc<<<32, 256>>>(0, 1, f1w, f1b, nullptr, 1024, 512, 1);
    k_fc<<<16, 256>>>(1, 2, f2w, f2b, nullptr, 512, 256, 1);
    k_fc<<<1, 32>>>(2, 3, f3w, f3b, (float*)d_out, 256, 1, 0);
}